// round 15
// baseline (speedup 1.0000x reference)
#include <cuda_runtime.h>
#include <cuda/atomic>

#define NSEQ 16384
#define HDIM 512
#define GDIM 2048
#define NCTA 64
#define TPB  256

// Scratch (device globals: no allocation allowed)
__device__ float g_XE[(size_t)NSEQ * GDIM];   // encoder x-part, bias folded
__device__ float g_XD[(size_t)NSEQ * GDIM];   // decoder x-part rows 1..N-1, bias folded
// {h_bits:32 | epoch:32} per unit, x2 parity, one 32B sector per pair (R13).
__device__ unsigned long long g_pair[2][HDIM][4];

// ---------------------------------------------------------------------------
// init: parity 0 = {h=0.0f, epoch=0} (valid h_0); parity 1 = epoch ~0.
// ---------------------------------------------------------------------------
__global__ void init_kernel() {
    int t = threadIdx.x;
    if (t < HDIM) {
        g_pair[0][t][0] = 0ull;                    // h bits 0.0f, epoch 0
        g_pair[1][t][0] = 0x00000000FFFFFFFFull;   // epoch 0xFFFFFFFF
    }
}

// ---------------------------------------------------------------------------
// GEMM: OUT[m][n] = sum_k A[m][ak(k)] * W[n][k] + b1[n] + b2[n]
// FLIP reverses A's feature index (decoder input), targets g_XD rows 1..N-1.
// ---------------------------------------------------------------------------
template <bool FLIP>
__global__ __launch_bounds__(256, 2) void gemm_xpart(
    const float* __restrict__ A, const float* __restrict__ W,
    const float* __restrict__ b1, const float* __restrict__ b2, int Mlim)
{
    __shared__ float As[16][132];
    __shared__ float Ws[16][132];
    float* OUT = FLIP ? (g_XD + GDIM) : g_XE;

    const int bn = blockIdx.x, bm = blockIdx.y;
    const int tid = threadIdx.x;
    const int tx = tid & 15, ty = tid >> 4;

    float acc[8][8];
#pragma unroll
    for (int i = 0; i < 8; i++)
#pragma unroll
        for (int j = 0; j < 8; j++) acc[i][j] = 0.f;

    for (int k0 = 0; k0 < 512; k0 += 16) {
#pragma unroll
        for (int l = 0; l < 2; l++) {
            int fid = tid + l * 256;
            int r = fid >> 2, c4 = fid & 3;
            int gm = bm * 128 + r;
            float4 v = make_float4(0.f, 0.f, 0.f, 0.f);
            if (gm < Mlim) {
                if (!FLIP) {
                    v = *(const float4*)(A + (size_t)gm * 512 + k0 + c4 * 4);
                } else {
                    float4 w = *(const float4*)(A + (size_t)gm * 512 + (508 - k0 - c4 * 4));
                    v = make_float4(w.w, w.z, w.y, w.x);
                }
            }
            As[c4 * 4 + 0][r] = v.x; As[c4 * 4 + 1][r] = v.y;
            As[c4 * 4 + 2][r] = v.z; As[c4 * 4 + 3][r] = v.w;
        }
#pragma unroll
        for (int l = 0; l < 2; l++) {
            int fid = tid + l * 256;
            int r = fid >> 2, c4 = fid & 3;
            int gn = bn * 128 + r;
            float4 v = *(const float4*)(W + (size_t)gn * 512 + k0 + c4 * 4);
            Ws[c4 * 4 + 0][r] = v.x; Ws[c4 * 4 + 1][r] = v.y;
            Ws[c4 * 4 + 2][r] = v.z; Ws[c4 * 4 + 3][r] = v.w;
        }
        __syncthreads();
#pragma unroll
        for (int k = 0; k < 16; k++) {
            float ra[8], rb[8];
#pragma unroll
            for (int i = 0; i < 8; i++) ra[i] = As[k][ty * 8 + i];
#pragma unroll
            for (int j = 0; j < 8; j++) rb[j] = Ws[k][tx * 8 + j];
#pragma unroll
            for (int i = 0; i < 8; i++)
#pragma unroll
                for (int j = 0; j < 8; j++) acc[i][j] = fmaf(ra[i], rb[j], acc[i][j]);
        }
        __syncthreads();
    }

    float bj[8];
#pragma unroll
    for (int j = 0; j < 8; j++) {
        int gn = bn * 128 + tx * 8 + j;
        bj[j] = b1[gn] + b2[gn];
    }
#pragma unroll
    for (int i = 0; i < 8; i++) {
        int gm = bm * 128 + ty * 8 + i;
        if (gm < Mlim) {
            float* o = OUT + (size_t)gm * GDIM + bn * 128 + tx * 8;
            *(float4*)(o) = make_float4(acc[i][0] + bj[0], acc[i][1] + bj[1],
                                        acc[i][2] + bj[2], acc[i][3] + bj[3]);
            *(float4*)(o + 4) = make_float4(acc[i][4] + bj[4], acc[i][5] + bj[5],
                                            acc[i][6] + bj[6], acc[i][7] + bj[7]);
        }
    }
}

// ---------------------------------------------------------------------------
// Persistent recurrent scan, R15 structure: 64 CTAs x 8 units, warp w owns
// unit w's FOUR gates (lane l: gate g=l>>3, k-seg seg=l&7, 64 h elems each).
// Gate->cell tail is warp-local (shfl), so each step needs only ONE barrier
// and no gate SMEM. Comm protocol unchanged from R13/R14: sector-padded
// relaxed {h|epoch} pairs, 2 polls/thread, pure spin.
// ---------------------------------------------------------------------------
__device__ __forceinline__ float sigm_(float x) { return 1.f / (1.f + __expf(-x)); }
__device__ __forceinline__ float tanh_(float x) { return 2.f / (1.f + __expf(-2.f * x)) - 1.f; }

__global__ __launch_bounds__(TPB, 1) void lstm_scan(
    const float* __restrict__ Whh_e, const float* __restrict__ Whh_d,
    const float* __restrict__ Wih_d, const float* __restrict__ bih_d,
    const float* __restrict__ bhh_d, float* __restrict__ out)
{
    const int cta = blockIdx.x;
    const int t = threadIdx.x;
    const int w = t >> 5;                          // warp = local unit (0..7)
    const int l = t & 31;
    const int g = l >> 3;                          // gate (0..3)
    const int seg = l & 7;                         // k-segment (0..7), 64 elems
    const int unit = cta * 8 + w;                  // global unit (0..511)
    const int grow = g * HDIM + unit;              // gate-row in [0,2048)

    // Recurrent weights: 64 enc + 64 dec floats per thread, in registers.
    float we[64], wd[64];
    {
        const float4* pe = (const float4*)(Whh_e + (size_t)grow * HDIM + seg * 64);
        const float4* pd = (const float4*)(Whh_d + (size_t)grow * HDIM + seg * 64);
#pragma unroll
        for (int i = 0; i < 16; i++) {
            float4 a = pe[i];
            we[4 * i] = a.x; we[4 * i + 1] = a.y; we[4 * i + 2] = a.z; we[4 * i + 3] = a.w;
            float4 b = pd[i];
            wd[4 * i] = b.x; wd[4 * i + 1] = b.y; wd[4 * i + 2] = b.z; wd[4 * i + 3] = b.w;
        }
    }

    __shared__ __align__(16) float sh[2][HDIM];    // parity double-buffered h

    float c = 0.f;                                 // cell state (lane 0 of each warp)

    const bool rl = (seg == 0);                    // activation lane for row (g,unit)

    // x-part loader for a given step (1..2N); activation lanes only.
    auto load_x = [&](int stp) -> float {
        if (!rl || stp > 2 * NSEQ) return 0.f;
        const bool d2 = stp > NSEQ;
        const int s2 = d2 ? stp - NSEQ : stp;
        if (d2 && s2 == 1)
            return __ldg(bih_d + grow) + __ldg(bhh_d + grow);
        const float* xb = d2 ? (g_XD + (size_t)(s2 - 1) * GDIM)
                             : (g_XE + (size_t)(s2 - 1) * GDIM);
        return __ldg(xb + grow);
    };

    float xv_next = load_x(1);

#pragma unroll 1
    for (int step = 1; step <= 2 * NSEQ; ++step) {
        const bool dec = step > NSEQ;
        const int s = dec ? step - NSEQ : step;
        const bool xd0 = dec && (s == 1);
        const int pc = (step - 1) & 1;             // consume parity
        const int pp = step & 1;                   // produce parity

        const float xv = xv_next;
        xv_next = load_x(step + 1);

        // Poll h_{step-1}: 2 strong relaxed 8B loads per thread, pure spin.
        {
            const unsigned exp = (unsigned)(step - 1);
            cuda::atomic_ref<unsigned long long, cuda::thread_scope_device>
                p0(g_pair[pc][2 * t][0]);
            cuda::atomic_ref<unsigned long long, cuda::thread_scope_device>
                p1(g_pair[pc][2 * t + 1][0]);
            unsigned long long v0 = p0.load(cuda::memory_order_relaxed);
            unsigned long long v1 = p1.load(cuda::memory_order_relaxed);
            while ((unsigned)v0 != exp || (unsigned)v1 != exp) {
                v0 = p0.load(cuda::memory_order_relaxed);
                v1 = p1.load(cuda::memory_order_relaxed);
            }
            sh[pc][2 * t]     = __uint_as_float((unsigned)(v0 >> 32));
            sh[pc][2 * t + 1] = __uint_as_float((unsigned)(v1 >> 32));
        }
        __syncthreads();                           // the ONLY barrier per step

        // Partial dot: 64 MACs against register weights
        float a0 = 0.f, a1 = 0.f, a2 = 0.f, a3 = 0.f;
        const float4* sh4 = (const float4*)sh[pc] + seg * 16;
        if (!dec) {
#pragma unroll
            for (int i = 0; i < 16; i++) {
                float4 h4 = sh4[i];
                a0 = fmaf(we[4 * i], h4.x, a0);
                a1 = fmaf(we[4 * i + 1], h4.y, a1);
                a2 = fmaf(we[4 * i + 2], h4.z, a2);
                a3 = fmaf(we[4 * i + 3], h4.w, a3);
            }
        } else {
#pragma unroll
            for (int i = 0; i < 16; i++) {
                float4 h4 = sh4[i];
                a0 = fmaf(wd[4 * i], h4.x, a0);
                a1 = fmaf(wd[4 * i + 1], h4.y, a1);
                a2 = fmaf(wd[4 * i + 2], h4.z, a2);
                a3 = fmaf(wd[4 * i + 3], h4.w, a3);
            }
        }
        float sum = (a0 + a1) + (a2 + a3);

        // Decoder step 1: input is h_n itself -> add Wih_d . h_n inline
        if (xd0) {
            const float4* pw = (const float4*)(Wih_d + (size_t)grow * HDIM + seg * 64);
            float c0 = 0.f, c1 = 0.f, c2 = 0.f, c3 = 0.f;
#pragma unroll
            for (int i = 0; i < 16; i++) {
                float4 w4 = pw[i];
                float4 h4 = sh4[i];
                c0 = fmaf(w4.x, h4.x, c0);
                c1 = fmaf(w4.y, h4.y, c1);
                c2 = fmaf(w4.z, h4.z, c2);
                c3 = fmaf(w4.w, h4.w, c3);
            }
            sum += (c0 + c1) + (c2 + c3);
        }

        // Reduce over 8 k-segments (within each 8-lane gate group)
        sum += __shfl_xor_sync(0xffffffffu, sum, 1);
        sum += __shfl_xor_sync(0xffffffffu, sum, 2);
        sum += __shfl_xor_sync(0xffffffffu, sum, 4);

        // Activation on lanes 0,8,16,24 (one per gate), then warp-local
        // gather into lane 0 — no SMEM, no second barrier.
        float act = 0.f;
        if (rl) {
            float red = sum + xv;
            act = (g == 2) ? tanh_(red) : sigm_(red);
        }
        float gi = __shfl_sync(0xffffffffu, act, 0);
        float gf = __shfl_sync(0xffffffffu, act, 8);
        float gg = __shfl_sync(0xffffffffu, act, 16);
        float go = __shfl_sync(0xffffffffu, act, 24);

        if (l == 0) {
            c = fmaf(gf, c, gi * gg);
            float hn = go * tanh_(c);

            // Publish {h | epoch} as ONE strong RELAXED store — flag IS data.
            unsigned long long pv =
                ((unsigned long long)__float_as_uint(hn) << 32) | (unsigned)step;
            cuda::atomic_ref<unsigned long long, cuda::thread_scope_device>
                pj(g_pair[pp][unit][0]);
            pj.store(pv, cuda::memory_order_relaxed);

            // Output DRAM stores AFTER the publish.
            if (dec) {
                out[HDIM + (size_t)(s - 1) * HDIM + (HDIM - 1 - unit)] = hn;
            } else if (step == NSEQ) {
                out[unit] = hn;  // h_n
            }
        }
        // single-barrier safety: sh[pc] rewrite at step+2 staging happens
        // after sync(step+1), which follows every read of sh[pc] at step.
    }
}

// ---------------------------------------------------------------------------
extern "C" void kernel_launch(void* const* d_in, const int* in_sizes, int n_in,
                              void* d_out, int out_size)
{
    const float* x     = (const float*)d_in[0];
    const float* Wih_e = (const float*)d_in[1];
    const float* Whh_e = (const float*)d_in[2];
    const float* bih_e = (const float*)d_in[3];
    const float* bhh_e = (const float*)d_in[4];
    const float* Wih_d = (const float*)d_in[5];
    const float* Whh_d = (const float*)d_in[6];
    const float* bih_d = (const float*)d_in[7];
    const float* bhh_d = (const float*)d_in[8];
    float* out = (float*)d_out;

    init_kernel<<<1, 1024>>>();

    dim3 gg(GDIM / 128, NSEQ / 128);
    gemm_xpart<false><<<gg, 256>>>(x, Wih_e, bih_e, bhh_e, NSEQ);
    gemm_xpart<true ><<<gg, 256>>>(x, Wih_d, bih_d, bhh_d, NSEQ - 1);

    lstm_scan<<<NCTA, TPB>>>(Whh_e, Whh_d, Wih_d, bih_d, bhh_d, out);
}

// round 16
// speedup vs baseline: 1.9414x; 1.9414x over previous
#include <cuda_runtime.h>
#include <cuda/atomic>

#define NSEQ 16384
#define HDIM 512
#define GDIM 2048
#define NCTA 128
#define TPB  512

// Scratch (device globals: no allocation allowed)
__device__ float g_XE[(size_t)NSEQ * GDIM];   // encoder x-part, bias folded
__device__ float g_XD[(size_t)NSEQ * GDIM];   // decoder x-part rows 1..N-1, bias folded
// {h_bits:32 | epoch:32} per unit, x2 parity, one 32B sector per pair (R13).
__device__ unsigned long long g_pair[2][HDIM][4];

// ---------------------------------------------------------------------------
// init: parity 0 = {h=0.0f, epoch=0} (valid h_0); parity 1 = epoch ~0.
// ---------------------------------------------------------------------------
__global__ void init_kernel() {
    int t = threadIdx.x;
    if (t < HDIM) {
        g_pair[0][t][0] = 0ull;                    // h bits 0.0f, epoch 0
        g_pair[1][t][0] = 0x00000000FFFFFFFFull;   // epoch 0xFFFFFFFF
    }
}

// ---------------------------------------------------------------------------
// GEMM: OUT[m][n] = sum_k A[m][ak(k)] * W[n][k] + b1[n] + b2[n]
// FLIP reverses A's feature index (decoder input), targets g_XD rows 1..N-1.
// ---------------------------------------------------------------------------
template <bool FLIP>
__global__ __launch_bounds__(256, 2) void gemm_xpart(
    const float* __restrict__ A, const float* __restrict__ W,
    const float* __restrict__ b1, const float* __restrict__ b2, int Mlim)
{
    __shared__ float As[16][132];
    __shared__ float Ws[16][132];
    float* OUT = FLIP ? (g_XD + GDIM) : g_XE;

    const int bn = blockIdx.x, bm = blockIdx.y;
    const int tid = threadIdx.x;
    const int tx = tid & 15, ty = tid >> 4;

    float acc[8][8];
#pragma unroll
    for (int i = 0; i < 8; i++)
#pragma unroll
        for (int j = 0; j < 8; j++) acc[i][j] = 0.f;

    for (int k0 = 0; k0 < 512; k0 += 16) {
#pragma unroll
        for (int l = 0; l < 2; l++) {
            int fid = tid + l * 256;
            int r = fid >> 2, c4 = fid & 3;
            int gm = bm * 128 + r;
            float4 v = make_float4(0.f, 0.f, 0.f, 0.f);
            if (gm < Mlim) {
                if (!FLIP) {
                    v = *(const float4*)(A + (size_t)gm * 512 + k0 + c4 * 4);
                } else {
                    float4 w = *(const float4*)(A + (size_t)gm * 512 + (508 - k0 - c4 * 4));
                    v = make_float4(w.w, w.z, w.y, w.x);
                }
            }
            As[c4 * 4 + 0][r] = v.x; As[c4 * 4 + 1][r] = v.y;
            As[c4 * 4 + 2][r] = v.z; As[c4 * 4 + 3][r] = v.w;
        }
#pragma unroll
        for (int l = 0; l < 2; l++) {
            int fid = tid + l * 256;
            int r = fid >> 2, c4 = fid & 3;
            int gn = bn * 128 + r;
            float4 v = *(const float4*)(W + (size_t)gn * 512 + k0 + c4 * 4);
            Ws[c4 * 4 + 0][r] = v.x; Ws[c4 * 4 + 1][r] = v.y;
            Ws[c4 * 4 + 2][r] = v.z; Ws[c4 * 4 + 3][r] = v.w;
        }
        __syncthreads();
#pragma unroll
        for (int k = 0; k < 16; k++) {
            float ra[8], rb[8];
#pragma unroll
            for (int i = 0; i < 8; i++) ra[i] = As[k][ty * 8 + i];
#pragma unroll
            for (int j = 0; j < 8; j++) rb[j] = Ws[k][tx * 8 + j];
#pragma unroll
            for (int i = 0; i < 8; i++)
#pragma unroll
                for (int j = 0; j < 8; j++) acc[i][j] = fmaf(ra[i], rb[j], acc[i][j]);
        }
        __syncthreads();
    }

    float bj[8];
#pragma unroll
    for (int j = 0; j < 8; j++) {
        int gn = bn * 128 + tx * 8 + j;
        bj[j] = b1[gn] + b2[gn];
    }
#pragma unroll
    for (int i = 0; i < 8; i++) {
        int gm = bm * 128 + ty * 8 + i;
        if (gm < Mlim) {
            float* o = OUT + (size_t)gm * GDIM + bn * 128 + tx * 8;
            *(float4*)(o) = make_float4(acc[i][0] + bj[0], acc[i][1] + bj[1],
                                        acc[i][2] + bj[2], acc[i][3] + bj[3]);
            *(float4*)(o + 4) = make_float4(acc[i][4] + bj[4], acc[i][5] + bj[5],
                                            acc[i][6] + bj[6], acc[i][7] + bj[7]);
        }
    }
}

// ---------------------------------------------------------------------------
// Persistent recurrent scan — R14 protocol (sector-padded relaxed {h|epoch}
// pairs, pure spin, 2 barriers/step, t<4 tail), R16 decomposition: 512
// threads/CTA. Row li=t>>5 (16 gate-rows: gate=li>>2, unit=li&3), lane=k-seg
// (32 segs x 16 h elems). 16 weight regs per phase, 1 poll pair per thread,
// full-warp shfl reduce, activation on lane 0 of each warp.
// ---------------------------------------------------------------------------
__device__ __forceinline__ float sigm_(float x) { return 1.f / (1.f + __expf(-x)); }
__device__ __forceinline__ float tanh_(float x) { return 2.f / (1.f + __expf(-2.f * x)) - 1.f; }

__global__ __launch_bounds__(TPB, 1) void lstm_scan(
    const float* __restrict__ Whh_e, const float* __restrict__ Whh_d,
    const float* __restrict__ Wih_d, const float* __restrict__ bih_d,
    const float* __restrict__ bhh_d, float* __restrict__ out)
{
    const int cta = blockIdx.x;
    const int t = threadIdx.x;
    const int li = t >> 5;                        // gate-row (0..15) = warp id
    const int lane = t & 31;                      // k-segment (0..31), 16 elems
    const int gate = li >> 2, u = li & 3;
    const int grow = gate * HDIM + cta * 4 + u;   // gate-row in [0,2048)

    // Recurrent weights: 16 enc + 16 dec floats per thread, in registers.
    float we[16], wd[16];
    {
        const float4* pe = (const float4*)(Whh_e + (size_t)grow * HDIM + lane * 16);
        const float4* pd = (const float4*)(Whh_d + (size_t)grow * HDIM + lane * 16);
#pragma unroll
        for (int i = 0; i < 4; i++) {
            float4 a = pe[i];
            we[4 * i] = a.x; we[4 * i + 1] = a.y; we[4 * i + 2] = a.z; we[4 * i + 3] = a.w;
            float4 b = pd[i];
            wd[4 * i] = b.x; wd[4 * i + 1] = b.y; wd[4 * i + 2] = b.z; wd[4 * i + 3] = b.w;
        }
    }

    __shared__ __align__(16) float sh[2][HDIM];   // parity double-buffered h
    __shared__ float sred[2][16];                 // parity double-buffered gates

    float c = 0.f;  // cell state, valid in lanes t<4 (unit = t)

    const bool rl = (lane == 0);                  // activation lane of warp li

    // x-part loader for a given step (1..2N); activation lanes only.
    auto load_x = [&](int stp) -> float {
        if (!rl || stp > 2 * NSEQ) return 0.f;
        const bool d2 = stp > NSEQ;
        const int s2 = d2 ? stp - NSEQ : stp;
        if (d2 && s2 == 1)
            return __ldg(bih_d + grow) + __ldg(bhh_d + grow);
        const float* xb = d2 ? (g_XD + (size_t)(s2 - 1) * GDIM)
                             : (g_XE + (size_t)(s2 - 1) * GDIM);
        return __ldg(xb + grow);
    };

    float xv_next = load_x(1);

#pragma unroll 1
    for (int step = 1; step <= 2 * NSEQ; ++step) {
        const bool dec = step > NSEQ;
        const int s = dec ? step - NSEQ : step;
        const bool xd0 = dec && (s == 1);
        const int pc = (step - 1) & 1;            // consume parity
        const int pp = step & 1;                  // produce parity

        const float xv = xv_next;
        xv_next = load_x(step + 1);

        // Poll h_{step-1}: ONE strong relaxed 8B load per thread (512
        // threads <-> 512 pairs), pure spin; flag IS the data.
        {
            const unsigned exp = (unsigned)(step - 1);
            cuda::atomic_ref<unsigned long long, cuda::thread_scope_device>
                p0(g_pair[pc][t][0]);
            unsigned long long v0 = p0.load(cuda::memory_order_relaxed);
            while ((unsigned)v0 != exp)
                v0 = p0.load(cuda::memory_order_relaxed);
            sh[pc][t] = __uint_as_float((unsigned)(v0 >> 32));
        }
        __syncthreads();                                  // sync 1: sh ready

        // Partial dot: 16 MACs against register weights
        float a0 = 0.f, a1 = 0.f, a2 = 0.f, a3 = 0.f;
        const float4* sh4 = (const float4*)sh[pc] + lane * 4;
        if (!dec) {
#pragma unroll
            for (int i = 0; i < 4; i++) {
                float4 h4 = sh4[i];
                a0 = fmaf(we[4 * i], h4.x, a0);
                a1 = fmaf(we[4 * i + 1], h4.y, a1);
                a2 = fmaf(we[4 * i + 2], h4.z, a2);
                a3 = fmaf(we[4 * i + 3], h4.w, a3);
            }
        } else {
#pragma unroll
            for (int i = 0; i < 4; i++) {
                float4 h4 = sh4[i];
                a0 = fmaf(wd[4 * i], h4.x, a0);
                a1 = fmaf(wd[4 * i + 1], h4.y, a1);
                a2 = fmaf(wd[4 * i + 2], h4.z, a2);
                a3 = fmaf(wd[4 * i + 3], h4.w, a3);
            }
        }
        float sum = (a0 + a1) + (a2 + a3);

        // Decoder step 1: input is h_n itself -> add Wih_d . h_n inline
        if (xd0) {
            const float4* pw = (const float4*)(Wih_d + (size_t)grow * HDIM + lane * 16);
            float c0 = 0.f, c1 = 0.f, c2 = 0.f, c3 = 0.f;
#pragma unroll
            for (int i = 0; i < 4; i++) {
                float4 w4 = pw[i];
                float4 h4 = sh4[i];
                c0 = fmaf(w4.x, h4.x, c0);
                c1 = fmaf(w4.y, h4.y, c1);
                c2 = fmaf(w4.z, h4.z, c2);
                c3 = fmaf(w4.w, h4.w, c3);
            }
            sum += (c0 + c1) + (c2 + c3);
        }

        // Full-warp reduce over the 32 k-segments of this gate-row
        sum += __shfl_xor_sync(0xffffffffu, sum, 1);
        sum += __shfl_xor_sync(0xffffffffu, sum, 2);
        sum += __shfl_xor_sync(0xffffffffu, sum, 4);
        sum += __shfl_xor_sync(0xffffffffu, sum, 8);
        sum += __shfl_xor_sync(0xffffffffu, sum, 16);

        // Activation on lane 0 of each of the 16 warps (parallel MUFU).
        if (rl) {
            float red = sum + xv;
            sred[pp][li] = (gate == 2) ? tanh_(red) : sigm_(red);
        }
        __syncthreads();                                  // sync 2: sred ready

        // Lanes 0..3 (unit u = t): c,h update -> publish FIRST, then out
        if (t < 4) {
            float gi = sred[pp][t],     gf = sred[pp][4 + t];
            float gg = sred[pp][8 + t], go = sred[pp][12 + t];
            c = fmaf(gf, c, gi * gg);
            float hn = go * tanh_(c);

            const int j = cta * 4 + t;

            // Publish {h | epoch} as ONE strong RELAXED store — flag IS data.
            unsigned long long pv =
                ((unsigned long long)__float_as_uint(hn) << 32) | (unsigned)step;
            cuda::atomic_ref<unsigned long long, cuda::thread_scope_device>
                pj(g_pair[pp][j][0]);
            pj.store(pv, cuda::memory_order_relaxed);

            // Output DRAM stores AFTER the publish.
            if (dec) {
                out[HDIM + (size_t)(s - 1) * HDIM + (HDIM - 1 - j)] = hn;  // feature flip
            } else if (step == NSEQ) {
                out[j] = hn;  // h_n
            }
        }
        // no sync 3: parity double-buffering (proof as in R8)
    }
}

// ---------------------------------------------------------------------------
extern "C" void kernel_launch(void* const* d_in, const int* in_sizes, int n_in,
                              void* d_out, int out_size)
{
    const float* x     = (const float*)d_in[0];
    const float* Wih_e = (const float*)d_in[1];
    const float* Whh_e = (const float*)d_in[2];
    const float* bih_e = (const float*)d_in[3];
    const float* bhh_e = (const float*)d_in[4];
    const float* Wih_d = (const float*)d_in[5];
    const float* Whh_d = (const float*)d_in[6];
    const float* bih_d = (const float*)d_in[7];
    const float* bhh_d = (const float*)d_in[8];
    float* out = (float*)d_out;

    init_kernel<<<1, 1024>>>();

    dim3 gg(GDIM / 128, NSEQ / 128);
    gemm_xpart<false><<<gg, 256>>>(x, Wih_e, bih_e, bhh_e, NSEQ);
    gemm_xpart<true ><<<gg, 256>>>(x, Wih_d, bih_d, bhh_d, NSEQ - 1);

    lstm_scan<<<NCTA, TPB>>>(Whh_e, Whh_d, Wih_d, bih_d, bhh_d, out);
}